// round 5
// baseline (speedup 1.0000x reference)
#include <cuda_runtime.h>
#include <cuda_bf16.h>
#include <cstddef>
#include <cstdint>

// Problem constants
constexpr int B  = 4;
constexpr int N  = 256;
constexpr int D  = 512;
constexpr int H  = 8;
constexpr int HD = 64;
constexpr int KSP = 25;          // max(1, int(256*0.1))
constexpr float EPS = 1e-5f;

// ---------------------------------------------------------------------------
// Scratch (device globals: no allocation allowed in kernel_launch)
// ---------------------------------------------------------------------------
__device__ float g_qkv_buf  [4 * 256 * 1536];
__device__ float g_att_buf  [4 * 256 * 512];
__device__ float g_a0_buf   [4 * 256 * 512];
__device__ float g_a1_buf   [4 * 128 * 512];
__device__ float g_a2_buf   [4 * 64  * 512];
__device__ float g_p1_buf   [4 * 256 * 256];
__device__ float g_p2_buf   [4 * 256 * 512];
__device__ float g_cur_buf  [4 * 128 * 512];
__device__ float g_fused_buf[4 * 256 * 1536];
__device__ float g_hier_buf [4 * 256 * 512];
__device__ float g_hi_buf   [4 * 256 * 512];
__device__ float g_hj_buf   [4 * 256 * 512];
__device__ float g_scores_buf[4 * 256 * 256];

// ---------------------------------------------------------------------------
// cp.async helpers (LDGSTS)
// ---------------------------------------------------------------------------
__device__ __forceinline__ void cp16(void* smem, const void* gmem)
{
    uint32_t sa = (uint32_t)__cvta_generic_to_shared(smem);
    asm volatile("cp.async.ca.shared.global [%0], [%1], 16;" :: "r"(sa), "l"(gmem));
}
__device__ __forceinline__ void cp_commit()
{
    asm volatile("cp.async.commit_group;");
}
template <int NLeft>
__device__ __forceinline__ void cp_wait()
{
    asm volatile("cp.async.wait_group %0;" :: "n"(NLeft));
}

// ---------------------------------------------------------------------------
// SGEMM: C[M,Nc] = act(A[M,K] @ W[K,Nc] + bias)
// Tile BMx64, BK=16, 256 threads, TM x 4 per-thread register block where
// TM = BM/16. Thread (tx=tid&15, ty=tid>>4) owns CONSECUTIVE rows
// m = ty*TM .. ty*TM+TM-1 and CONSECUTIVE cols n = tx*4 .. tx*4+3, so both
// smem fragments are LDS.128 and the epilogue is a float4 store.
// As is k-major [kk][m] (filled by LDG.128 -> STS transpose, software
// pipelined); Ws is [kk][n] (filled by cp.async). Double-buffered.
// Requires M%BM==0, Nc%64==0, K%16==0 (true for every call).
// ---------------------------------------------------------------------------
template <int BM>
__global__ void gemm_bias_act(const float* __restrict__ A,
                              const float* __restrict__ W,
                              const float* __restrict__ bias,
                              float* __restrict__ C,
                              int M, int K, int Nc, int act)
{
    constexpr int TM = BM / 16;
    constexpr int AS = BM + 4;               // row stride (floats), mult of 4
    constexpr int AR = BM / 64;              // A float4 loads per thread
    __shared__ __align__(16) float As[2][16][AS];   // [buf][kk][m]
    __shared__ __align__(16) float Ws[2][16][72];   // [buf][kk][n]
    const int tid = threadIdx.x;
    const int tx = tid & 15;
    const int ty = tid >> 4;
    const int m0 = blockIdx.y * BM;
    const int n0 = blockIdx.x * 64;

    const int a_m  = tid >> 2;            // 0..63 (+64 for second set)
    const int a_k4 = (tid & 3) * 4;       // 0,4,8,12
    const int w_kk = tid >> 4;            // 0..15
    const int w_n4 = (tid & 15) * 4;      // 0..60

    auto ldgA = [&](float4* r, int k0) {
#pragma unroll
        for (int i = 0; i < AR; i++)
            r[i] = *reinterpret_cast<const float4*>(
                A + (size_t)(m0 + a_m + 64 * i) * K + k0 + a_k4);
    };
    auto stsA = [&](int buf, const float4* r) {
#pragma unroll
        for (int i = 0; i < AR; i++) {
            As[buf][a_k4 + 0][a_m + 64 * i] = r[i].x;
            As[buf][a_k4 + 1][a_m + 64 * i] = r[i].y;
            As[buf][a_k4 + 2][a_m + 64 * i] = r[i].z;
            As[buf][a_k4 + 3][a_m + 64 * i] = r[i].w;
        }
    };
    auto cpW = [&](int buf, int k0) {
        cp16(&Ws[buf][w_kk][w_n4], W + (size_t)(k0 + w_kk) * Nc + n0 + w_n4);
        cp_commit();
    };

    const int nk = K >> 4;
    float4 aregs[AR], aregsN[AR];
    ldgA(aregs, 0);
    cpW(0, 0);
    stsA(0, aregs);

    float acc[TM][4] = {};

    for (int t = 0; t < nk; t++) {
        const int buf = t & 1;
        if (t + 1 < nk) {
            ldgA(aregsN, (t + 1) << 4);
            cpW(buf ^ 1, (t + 1) << 4);
            cp_wait<1>();
        } else {
            cp_wait<0>();
        }
        __syncthreads();
#pragma unroll
        for (int kk = 0; kk < 16; kk++) {
            float a[TM], w[4];
#pragma unroll
            for (int i = 0; i < TM; i += 4) {
                float4 av = *reinterpret_cast<const float4*>(&As[buf][kk][ty * TM + i]);
                a[i + 0] = av.x; a[i + 1] = av.y; a[i + 2] = av.z; a[i + 3] = av.w;
            }
            float4 wv = *reinterpret_cast<const float4*>(&Ws[buf][kk][tx * 4]);
            w[0] = wv.x; w[1] = wv.y; w[2] = wv.z; w[3] = wv.w;
#pragma unroll
            for (int i = 0; i < TM; i++)
#pragma unroll
                for (int j = 0; j < 4; j++)
                    acc[i][j] += a[i] * w[j];
        }
        if (t + 1 < nk)
            stsA(buf ^ 1, aregsN);
        __syncthreads();
    }

    float4 bv = make_float4(0.f, 0.f, 0.f, 0.f);
    if (bias) bv = *reinterpret_cast<const float4*>(bias + n0 + tx * 4);
#pragma unroll
    for (int i = 0; i < TM; i++) {
        int m = m0 + ty * TM + i;
        float4 v;
        v.x = acc[i][0] + bv.x;
        v.y = acc[i][1] + bv.y;
        v.z = acc[i][2] + bv.z;
        v.w = acc[i][3] + bv.w;
        if (act) {
            v.x = fmaxf(v.x, 0.f); v.y = fmaxf(v.y, 0.f);
            v.z = fmaxf(v.z, 0.f); v.w = fmaxf(v.w, 0.f);
        }
        *reinterpret_cast<float4*>(C + (size_t)m * Nc + n0 + tx * 4) = v;
    }
}

// Host-side dispatch: pick BM so block count is high.
static void launch_gemm(const float* A, const float* W, const float* bias,
                        float* C, int M, int K, int Nc, int act)
{
    if (M % 128 == 0 && ((size_t)(M / 128) * (Nc / 64) >= 148)) {
        gemm_bias_act<128><<<dim3(Nc / 64, M / 128), 256>>>(A, W, bias, C, M, K, Nc, act);
    } else {
        gemm_bias_act<64><<<dim3(Nc / 64, M / 64), 256>>>(A, W, bias, C, M, K, Nc, act);
    }
}

// ---------------------------------------------------------------------------
// Fused attention: one block = (b, h, 16 queries). Computes the full S row
// block in smem, exact full-row softmax, then P @ V. Nl in {64,128,256}.
// qkv layout [B,Nl,1536]: q at +0, k at +512, v at +1024, head h at h*64.
// ---------------------------------------------------------------------------
__global__ void attn_kernel(const float* __restrict__ qkv,
                            float* __restrict__ out, int Nl)
{
    const int b = blockIdx.z, h = blockIdx.y, q0 = blockIdx.x * 16;
    const int tid = threadIdx.x;
    const int tx = tid & 15;
    const int ty = tid >> 4;

    __shared__ float Qs[16][65];
    __shared__ float KVs[64][65];
    __shared__ float Ss[16][260];

    const float* base = qkv + (size_t)b * Nl * 1536;

    // Load Q tile: 16 x 64, one float4 per thread.
    {
        float4 q = *reinterpret_cast<const float4*>(
            base + (size_t)(q0 + ty) * 1536 + h * 64 + tx * 4);
        Qs[ty][tx * 4 + 0] = q.x;
        Qs[ty][tx * 4 + 1] = q.y;
        Qs[ty][tx * 4 + 2] = q.z;
        Qs[ty][tx * 4 + 3] = q.w;
    }

    // Phase 1: S = (Q K^T) * 0.125, chunks of 64 keys.
    for (int j0 = 0; j0 < Nl; j0 += 64) {
        __syncthreads();
#pragma unroll
        for (int r = 0; r < 4; r++) {
            int v = tid + r * 256;
            int row = v >> 4;
            int d4 = (v & 15) * 4;
            float4 k = *reinterpret_cast<const float4*>(
                base + (size_t)(j0 + row) * 1536 + 512 + h * 64 + d4);
            KVs[row][d4 + 0] = k.x;
            KVs[row][d4 + 1] = k.y;
            KVs[row][d4 + 2] = k.z;
            KVs[row][d4 + 3] = k.w;
        }
        __syncthreads();
        float acc[4] = {0.f, 0.f, 0.f, 0.f};
#pragma unroll
        for (int dd = 0; dd < 64; dd++) {
            float q = Qs[ty][dd];
#pragma unroll
            for (int u = 0; u < 4; u++)
                acc[u] += q * KVs[tx + 16 * u][dd];
        }
#pragma unroll
        for (int u = 0; u < 4; u++)
            Ss[ty][j0 + tx + 16 * u] = acc[u] * 0.125f;
    }
    __syncthreads();

    // Phase 2: softmax over each of the 16 rows (2 rows per warp).
    {
        const int wid = tid >> 5, lane = tid & 31;
#pragma unroll
        for (int rr = 0; rr < 2; rr++) {
            int r = wid * 2 + rr;
            float mx = -3.4e38f;
            for (int j = lane; j < Nl; j += 32) mx = fmaxf(mx, Ss[r][j]);
#pragma unroll
            for (int o = 16; o > 0; o >>= 1)
                mx = fmaxf(mx, __shfl_xor_sync(0xffffffffu, mx, o));
            float sum = 0.f;
            for (int j = lane; j < Nl; j += 32) {
                float e = __expf(Ss[r][j] - mx);
                Ss[r][j] = e;
                sum += e;
            }
#pragma unroll
            for (int o = 16; o > 0; o >>= 1)
                sum += __shfl_xor_sync(0xffffffffu, sum, o);
            float inv = 1.0f / sum;
            for (int j = lane; j < Nl; j += 32) Ss[r][j] *= inv;
        }
    }

    // Phase 3: O = P @ V, chunks of 64 keys (reuse KVs).
    float acc[4] = {0.f, 0.f, 0.f, 0.f};
    for (int j0 = 0; j0 < Nl; j0 += 64) {
        __syncthreads();
#pragma unroll
        for (int r = 0; r < 4; r++) {
            int v = tid + r * 256;
            int row = v >> 4;
            int d4 = (v & 15) * 4;
            float4 vv = *reinterpret_cast<const float4*>(
                base + (size_t)(j0 + row) * 1536 + 1024 + h * 64 + d4);
            KVs[row][d4 + 0] = vv.x;
            KVs[row][d4 + 1] = vv.y;
            KVs[row][d4 + 2] = vv.z;
            KVs[row][d4 + 3] = vv.w;
        }
        __syncthreads();
#pragma unroll
        for (int jj = 0; jj < 64; jj++) {
            float p = Ss[ty][j0 + jj];
#pragma unroll
            for (int u = 0; u < 4; u++)
                acc[u] += p * KVs[jj][tx + 16 * u];
        }
    }

#pragma unroll
    for (int u = 0; u < 4; u++)
        out[((size_t)b * Nl + q0 + ty) * 512 + h * 64 + tx + 16 * u] = acc[u];
}

// ---------------------------------------------------------------------------
// Pairwise pooling: cur[b,i,d] = 0.5*(p[b,2i,d]+p[b,2i+1,d])
// ---------------------------------------------------------------------------
__global__ void pool_kernel(const float* __restrict__ p, float* __restrict__ cur,
                            int Nh, int total)
{
    int idx = blockIdx.x * 256 + threadIdx.x;
    if (idx >= total) return;
    int d = idx & 511;
    int rest = idx >> 9;
    int i = rest % Nh;
    int b = rest / Nh;
    size_t base = ((size_t)b * (2 * Nh) + 2 * i) * 512 + d;
    cur[idx] = 0.5f * (p[base] + p[base + 512]);
}

// Upsample + concat into [B,N,1536]
__global__ void fuse_kernel(const float* __restrict__ a0,
                            const float* __restrict__ a1,
                            const float* __restrict__ a2,
                            float* __restrict__ fused)
{
    int idx = blockIdx.x * 256 + threadIdx.x;
    if (idx >= B * N * 1536) return;
    int c = idx % 1536;
    int n = (idx / 1536) & 255;
    int b = idx / (1536 * 256);
    float v;
    if (c < 512)       v = a0[((size_t)b * 256 + n) * 512 + c];
    else if (c < 1024) v = a1[((size_t)b * 128 + (n >> 1)) * 512 + (c - 512)];
    else               v = a2[((size_t)b * 64  + (n >> 2)) * 512 + (c - 1024)];
    fused[idx] = v;
}

// LayerNorm over D=512, in place. grid = B*N rows, 256 threads (2 elems each).
__global__ void ln_kernel(float* __restrict__ x, const float* __restrict__ g,
                          const float* __restrict__ bb)
{
    __shared__ float red[256];
    const int t = threadIdx.x;
    float* row = x + (size_t)blockIdx.x * 512;

    float v0 = row[t], v1 = row[t + 256];
    red[t] = v0 + v1;
    __syncthreads();
    for (int s = 128; s > 0; s >>= 1) {
        if (t < s) red[t] += red[t + s];
        __syncthreads();
    }
    float mean = red[0] * (1.0f / 512.0f);
    __syncthreads();
    float d0 = v0 - mean, d1 = v1 - mean;
    red[t] = d0 * d0 + d1 * d1;
    __syncthreads();
    for (int s = 128; s > 0; s >>= 1) {
        if (t < s) red[t] += red[t + s];
        __syncthreads();
    }
    float rstd = rsqrtf(red[0] * (1.0f / 512.0f) + EPS);
    row[t]       = d0 * rstd * g[t]       + bb[t];
    row[t + 256] = d1 * rstd * g[t + 256] + bb[t + 256];
}

// ---------------------------------------------------------------------------
// Edge scores: scores[b,i,j] = sigmoid(sum_d relu(hi[b,i,d]+hj[b,j,d])*We2[d] + be2)
// with zeroed diagonal. 32x32 output tile per block, 2x2 per thread.
// grid (N/32, N/32, B), 256 threads.
// ---------------------------------------------------------------------------
__global__ void score_kernel(const float* __restrict__ hi,
                             const float* __restrict__ hj,
                             const float* __restrict__ We2,
                             const float* __restrict__ be2,
                             float* __restrict__ scores)
{
    const int b  = blockIdx.z;
    const int i0 = blockIdx.y * 32;
    const int j0 = blockIdx.x * 32;
    const int tid = threadIdx.x;
    const int r2 = tid >> 4;     // 0..15: owns rows r2, r2+16
    const int c2 = tid & 15;     // 0..15: owns cols c2, c2+16

    __shared__ float His[32][65];
    __shared__ float Hjs[32][65];
    __shared__ float w2[64];

    float acc[2][2] = {};

    for (int d0 = 0; d0 < 512; d0 += 64) {
        // Load 32x64 chunks of hi and hj (2 float4 each per thread).
#pragma unroll
        for (int r = 0; r < 2; r++) {
            int v = tid + r * 256;
            int row = v >> 4;
            int d4 = (v & 15) * 4;
            float4 a = *reinterpret_cast<const float4*>(
                hi + ((size_t)b * 256 + i0 + row) * 512 + d0 + d4);
            His[row][d4 + 0] = a.x; His[row][d4 + 1] = a.y;
            His[row][d4 + 2] = a.z; His[row][d4 + 3] = a.w;
            float4 c = *reinterpret_cast<const float4*>(
                hj + ((size_t)b * 256 + j0 + row) * 512 + d0 + d4);
            Hjs[row][d4 + 0] = c.x; Hjs[row][d4 + 1] = c.y;
            Hjs[row][d4 + 2] = c.z; Hjs[row][d4 + 3] = c.w;
        }
        if (tid < 64) w2[tid] = We2[d0 + tid];
        __syncthreads();
#pragma unroll 4
        for (int dd = 0; dd < 64; dd++) {
            float w  = w2[dd];
            float h0 = His[r2][dd],      h1 = His[r2 + 16][dd];
            float g0 = Hjs[c2][dd],      g1 = Hjs[c2 + 16][dd];
            acc[0][0] += fmaxf(h0 + g0, 0.0f) * w;
            acc[0][1] += fmaxf(h0 + g1, 0.0f) * w;
            acc[1][0] += fmaxf(h1 + g0, 0.0f) * w;
            acc[1][1] += fmaxf(h1 + g1, 0.0f) * w;
        }
        __syncthreads();
    }

    float bias = be2[0];
#pragma unroll
    for (int a = 0; a < 2; a++) {
#pragma unroll
        for (int c = 0; c < 2; c++) {
            int i = i0 + r2 + 16 * a;
            int j = j0 + c2 + 16 * c;
            float s = (i == j) ? 0.0f
                               : 1.0f / (1.0f + __expf(-(acc[a][c] + bias)));
            scores[((size_t)b * 256 + i) * 256 + j] = s;
        }
    }
}

// Exact stable top-k (value desc, index asc) -> one-hot adjacency.
// grid = B*N rows, 256 threads.
__global__ void topk_kernel(const float* __restrict__ scores,
                            float* __restrict__ out_adj)
{
    __shared__ float s[256];
    const int t = threadIdx.x;
    const float* row = scores + (size_t)blockIdx.x * 256;
    float v = row[t];
    s[t] = v;
    __syncthreads();
    int rank = 0;
#pragma unroll 8
    for (int j = 0; j < 256; j++) {
        float o = s[j];
        rank += (o > v) || (o == v && j < t);
    }
    out_adj[(size_t)blockIdx.x * 256 + t] = (rank < KSP) ? 1.0f : 0.0f;
}

// ---------------------------------------------------------------------------
// Host orchestration
// ---------------------------------------------------------------------------
static float* devptr(const void* sym)
{
    void* p = nullptr;
    cudaGetSymbolAddress(&p, sym);
    return (float*)p;
}

static void run_mha(const float* inp, int Nl,
                    const float* Wqkv, const float* bqkv,
                    const float* Wo, const float* bo,
                    float* qkv, float* att, float* out)
{
    int M = B * Nl;
    launch_gemm(inp, Wqkv, bqkv, qkv, M, 512, 1536, 0);
    attn_kernel<<<dim3(Nl / 16, H, B), 256>>>(qkv, att, Nl);
    launch_gemm(att, Wo, bo, out, M, 512, 512, 0);
}

extern "C" void kernel_launch(void* const* d_in, const int* in_sizes, int n_in,
                              void* d_out, int out_size)
{
    const float* x      = (const float*)d_in[0];
    // d_in[1] = adjacency (unused by the reference)
    const float* Wqkv   = (const float*)d_in[2];
    const float* bqkv   = (const float*)d_in[3];
    const float* Wo     = (const float*)d_in[4];
    const float* bo     = (const float*)d_in[5];
    const float* Wp1    = (const float*)d_in[6];
    const float* bp1    = (const float*)d_in[7];
    const float* Wp2    = (const float*)d_in[8];
    const float* bp2    = (const float*)d_in[9];
    const float* Wfuse  = (const float*)d_in[10];
    const float* bfuse  = (const float*)d_in[11];
    const float* ln_g   = (const float*)d_in[12];
    const float* ln_b   = (const float*)d_in[13];
    const float* We1    = (const float*)d_in[14];
    const float* be1    = (const float*)d_in[15];
    const float* We2    = (const float*)d_in[16];
    const float* be2    = (const float*)d_in[17];
    const float* Ws_qkv = (const float*)d_in[18];
    const float* bs_qkv = (const float*)d_in[19];
    const float* Ws_o   = (const float*)d_in[20];
    const float* bs_o   = (const float*)d_in[21];

    float* out_att = (float*)d_out;                       // [B,N,D]
    float* out_adj = (float*)d_out + (size_t)B * N * D;   // [B,N,N]

    float* qkv   = devptr(g_qkv_buf);
    float* att   = devptr(g_att_buf);
    float* a0    = devptr(g_a0_buf);
    float* a1    = devptr(g_a1_buf);
    float* a2    = devptr(g_a2_buf);
    float* p1    = devptr(g_p1_buf);
    float* p2    = devptr(g_p2_buf);
    float* curb  = devptr(g_cur_buf);
    float* fused = devptr(g_fused_buf);
    float* hier  = devptr(g_hier_buf);
    float* hi    = devptr(g_hi_buf);
    float* hj    = devptr(g_hj_buf);
    float* sc    = devptr(g_scores_buf);

    float* aouts[3] = {a0, a1, a2};
    const float* cur = x;

    // --- hierarchical levels ---
    for (int l = 0; l < 3; l++) {
        int Nl = 256 >> l;
        run_mha(cur, Nl,
                Wqkv + (size_t)l * 512 * 1536, bqkv + (size_t)l * 1536,
                Wo + (size_t)l * 512 * 512,   bo + (size_t)l * 512,
                qkv, att, aouts[l]);
        if (l < 2) {
            int M = B * Nl;
            launch_gemm(aouts[l], Wp1 + (size_t)l * 512 * 256,
                        bp1 + (size_t)l * 256, p1, M, 512, 256, 1);
            launch_gemm(p1, Wp2 + (size_t)l * 256 * 512,
                        bp2 + (size_t)l * 512, p2, M, 256, 512, 0);
            int Nh = Nl / 2;
            int total = B * Nh * 512;
            pool_kernel<<<(total + 255) / 256, 256>>>(p2, curb, Nh, total);
            cur = curb;
        }
    }

    // --- fuse + LN ---
    fuse_kernel<<<(B * N * 1536 + 255) / 256, 256>>>(a0, a1, a2, fused);
    launch_gemm(fused, Wfuse, bfuse, hier, 1024, 1536, 512, 1);
    ln_kernel<<<B * N, 256>>>(hier, ln_g, ln_b);

    // --- sparse edge scoring + top-k ---
    launch_gemm(hier, We1, nullptr, hi, 1024, 512, 512, 0);
    launch_gemm(hier, We1 + 512 * 512, be1, hj, 1024, 512, 512, 0);
    score_kernel<<<dim3(8, 8, 4), 256>>>(hi, hj, We2, be2, sc);
    topk_kernel<<<B * N, 256>>>(sc, out_adj);

    // --- final sparse-branch MHA -> output ---
    run_mha(hier, 256, Ws_qkv, bs_qkv, Ws_o, bs_o, qkv, att, out_att);
}